// round 15
// baseline (speedup 1.0000x reference)
#include <cuda_runtime.h>
#include <cuda_bf16.h>
#include <cstdint>

// Problem constants
#define B_SZ   2
#define S_SZ   2048
#define DM     1024
#define NH     16
#define DK     64
#define BS     (B_SZ * S_SZ)          // 4096 rows

#define KTV_CHUNKS 32

// Scratch (no cudaMalloc allowed -> device globals)
__device__ float g_Q[BS * DM];
__device__ float g_K[BS * DM];
__device__ float g_V[BS * DM];
__device__ float g_O[BS * DM];
__device__ float g_M[B_SZ * NH * DK * DK];
__device__ float g_Mpart[B_SZ * NH][KTV_CHUNKS][DK * DK];

// ---------------------------------------------------------------------------
// tf32 mma.sync GEMM: C[M,N] = A[M,K] * W[N,K]^T  (row-major, K contiguous)
// CTA tile 128x256, k-tile 32, 8 warps (2m x 4n), warp tile 64x64.
// Double-buffered smem (SPAD=36 word rows -> conflict-free fragment LDS).
// ---------------------------------------------------------------------------
#define TBM 128
#define TBN 256
#define TBK 32
#define NKT (DM / TBK)       // 32
#define SPAD 36
#define SM_DYN (2 * (TBM + TBN) * SPAD * 4)   // 110592 bytes

__device__ __forceinline__ uint32_t f2tf32(float f) {
    uint32_t r;
    asm("cvt.rna.tf32.f32 %0, %1;" : "=r"(r) : "f"(f));
    return r;
}

__device__ __forceinline__ void mma_tf32(float* c, const uint32_t* a, const uint32_t* b) {
    asm volatile(
        "mma.sync.aligned.m16n8k8.row.col.f32.tf32.tf32.f32 "
        "{%0,%1,%2,%3}, {%4,%5,%6,%7}, {%8,%9}, {%0,%1,%2,%3};\n"
        : "+f"(c[0]), "+f"(c[1]), "+f"(c[2]), "+f"(c[3])
        : "r"(a[0]), "r"(a[1]), "r"(a[2]), "r"(a[3]), "r"(b[0]), "r"(b[1]));
}

__device__ __forceinline__
void gemm_body(const float* __restrict__ A, const float* __restrict__ W,
               float* __restrict__ C, int bm, int bn)
{
    extern __shared__ uint32_t sm[];
    uint32_t* As = sm;                        // [2][128][SPAD]
    uint32_t* Ws = sm + 2 * TBM * SPAD;       // [2][256][SPAD]

    const int tid  = threadIdx.x;
    const int lane = tid & 31;
    const int wid  = tid >> 5;
    const int g    = lane >> 2;       // 0..7
    const int t    = lane & 3;        // 0..3
    const int wm   = wid >> 2;        // 0..1  (64-row m-tile)
    const int wn   = wid & 3;         // 0..3  (64-col n-tile)

    float acc[4][8][4];
#pragma unroll
    for (int mi = 0; mi < 4; ++mi)
#pragma unroll
        for (int ni = 0; ni < 8; ++ni)
#pragma unroll
            for (int e = 0; e < 4; ++e) acc[mi][ni][e] = 0.0f;

    float4 ar[4], br[8];

    // ---- prologue: load + store tile 0 into buffer 0 ----
#pragma unroll
    for (int i = 0; i < 4; ++i) {                       // A: 128x32 = 1024 float4
        int idx = tid + i * 256;
        int r = idx >> 3, c = (idx & 7) * 4;
        ar[i] = *reinterpret_cast<const float4*>(&A[(size_t)(bm + r) * DM + c]);
    }
#pragma unroll
    for (int i = 0; i < 8; ++i) {                       // B: 256x32 = 2048 float4
        int idx = tid + i * 256;
        int r = idx >> 3, c = (idx & 7) * 4;
        br[i] = *reinterpret_cast<const float4*>(&W[(size_t)(bn + r) * DM + c]);
    }
#pragma unroll
    for (int i = 0; i < 4; ++i) {
        int idx = tid + i * 256;
        int r = idx >> 3, c = (idx & 7) * 4;
        uint4 tv = {f2tf32(ar[i].x), f2tf32(ar[i].y), f2tf32(ar[i].z), f2tf32(ar[i].w)};
        *reinterpret_cast<uint4*>(&As[r * SPAD + c]) = tv;
    }
#pragma unroll
    for (int i = 0; i < 8; ++i) {
        int idx = tid + i * 256;
        int r = idx >> 3, c = (idx & 7) * 4;
        uint4 tv = {f2tf32(br[i].x), f2tf32(br[i].y), f2tf32(br[i].z), f2tf32(br[i].w)};
        *reinterpret_cast<uint4*>(&Ws[r * SPAD + c]) = tv;
    }
    __syncthreads();

    for (int kt = 0; kt < NKT; ++kt) {
        const uint32_t* Ab = As + (kt & 1) * TBM * SPAD;
        const uint32_t* Wb = Ws + (kt & 1) * TBN * SPAD;

        // issue next tile's global loads (overlap with compute below)
        if (kt + 1 < NKT) {
            const int k0 = (kt + 1) * TBK;
#pragma unroll
            for (int i = 0; i < 4; ++i) {
                int idx = tid + i * 256;
                int r = idx >> 3, c = (idx & 7) * 4;
                ar[i] = *reinterpret_cast<const float4*>(&A[(size_t)(bm + r) * DM + k0 + c]);
            }
#pragma unroll
            for (int i = 0; i < 8; ++i) {
                int idx = tid + i * 256;
                int r = idx >> 3, c = (idx & 7) * 4;
                br[i] = *reinterpret_cast<const float4*>(&W[(size_t)(bn + r) * DM + k0 + c]);
            }
        }

        // ---- compute: 4 k-steps of 8 ----
#pragma unroll
        for (int ks = 0; ks < 4; ++ks) {
            const int kk = ks * 8;
            uint32_t af[4][4];
#pragma unroll
            for (int mi = 0; mi < 4; ++mi) {
                int m = wm * 64 + mi * 16 + g;
                af[mi][0] = Ab[m * SPAD + kk + t];
                af[mi][1] = Ab[(m + 8) * SPAD + kk + t];
                af[mi][2] = Ab[m * SPAD + kk + t + 4];
                af[mi][3] = Ab[(m + 8) * SPAD + kk + t + 4];
            }
            uint32_t bf[8][2];
#pragma unroll
            for (int ni = 0; ni < 8; ++ni) {
                int n = wn * 64 + ni * 8 + g;
                bf[ni][0] = Wb[n * SPAD + kk + t];
                bf[ni][1] = Wb[n * SPAD + kk + t + 4];
            }
#pragma unroll
            for (int mi = 0; mi < 4; ++mi)
#pragma unroll
                for (int ni = 0; ni < 8; ++ni)
                    mma_tf32(acc[mi][ni], af[mi], bf[ni]);
        }

        // ---- store next tile into the other buffer ----
        if (kt + 1 < NKT) {
            uint32_t* An = As + ((kt + 1) & 1) * TBM * SPAD;
            uint32_t* Wn = Ws + ((kt + 1) & 1) * TBN * SPAD;
#pragma unroll
            for (int i = 0; i < 4; ++i) {
                int idx = tid + i * 256;
                int r = idx >> 3, c = (idx & 7) * 4;
                uint4 tv = {f2tf32(ar[i].x), f2tf32(ar[i].y), f2tf32(ar[i].z), f2tf32(ar[i].w)};
                *reinterpret_cast<uint4*>(&An[r * SPAD + c]) = tv;
            }
#pragma unroll
            for (int i = 0; i < 8; ++i) {
                int idx = tid + i * 256;
                int r = idx >> 3, c = (idx & 7) * 4;
                uint4 tv = {f2tf32(br[i].x), f2tf32(br[i].y), f2tf32(br[i].z), f2tf32(br[i].w)};
                *reinterpret_cast<uint4*>(&Wn[r * SPAD + c]) = tv;
            }
            __syncthreads();
        }
    }

    // ---- epilogue ----
#pragma unroll
    for (int mi = 0; mi < 4; ++mi) {
#pragma unroll
        for (int ni = 0; ni < 8; ++ni) {
            int row = bm + wm * 64 + mi * 16 + g;
            int col = bn + wn * 64 + ni * 8 + 2 * t;
            *reinterpret_cast<float2*>(&C[(size_t)row * DM + col]) =
                make_float2(acc[mi][ni][0], acc[mi][ni][1]);
            *reinterpret_cast<float2*>(&C[(size_t)(row + 8) * DM + col]) =
                make_float2(acc[mi][ni][2], acc[mi][ni][3]);
        }
    }
}

// Merged Q/K/V projection: blockIdx.z selects which projection
__global__ __launch_bounds__(256, 1)
void qkv_gemm(const float* __restrict__ q, const float* __restrict__ k,
              const float* __restrict__ v,
              const float* __restrict__ Wq, const float* __restrict__ Wk,
              const float* __restrict__ Wv)
{
    const float* A;
    const float* W;
    float* C;
    if (blockIdx.z == 0)      { A = q; W = Wq; C = g_Q; }
    else if (blockIdx.z == 1) { A = k; W = Wk; C = g_K; }
    else                      { A = v; W = Wv; C = g_V; }
    gemm_body(A, W, C, blockIdx.y * TBM, blockIdx.x * TBN);
}

__global__ __launch_bounds__(256, 1)
void out_gemm(const float* __restrict__ Wo, float* __restrict__ out)
{
    gemm_body(g_O, Wo, out, blockIdx.y * TBM, blockIdx.x * TBN);
}

// ---------------------------------------------------------------------------
// ktv partial: P[bh][chunk][d1][d2] = sum_{s in chunk} K[b,s,h,d1]*V[b,s,h,d2]
// ---------------------------------------------------------------------------
__global__ __launch_bounds__(256)
void ktv_partial(const float* __restrict__ Km, const float* __restrict__ Vm)
{
    const int chunk = blockIdx.x;
    const int bh = blockIdx.y;
    const int b = bh >> 4, h = bh & 15;
    const int sbase = chunk * (S_SZ / KTV_CHUNKS);
    const float* Kb = Km + (size_t)b * S_SZ * DM + h * DK;
    const float* Vb = Vm + (size_t)b * S_SZ * DM + h * DK;

    __shared__ float Ks[32][DK];
    __shared__ float Vs[32][DK];

    const int tid = threadIdx.x;
    const int tx = tid & 15;
    const int ty = tid >> 4;

    float acc[4][4];
#pragma unroll
    for (int i = 0; i < 4; ++i)
#pragma unroll
        for (int j = 0; j < 4; ++j) acc[i][j] = 0.0f;

    for (int s0 = sbase; s0 < sbase + S_SZ / KTV_CHUNKS; s0 += 32) {
#pragma unroll
        for (int i = 0; i < 2; ++i) {
            int idx = tid + i * 256;
            int r = idx >> 4;
            int c = (idx & 15) * 4;
            *reinterpret_cast<float4*>(&Ks[r][c]) =
                *reinterpret_cast<const float4*>(&Kb[(size_t)(s0 + r) * DM + c]);
            *reinterpret_cast<float4*>(&Vs[r][c]) =
                *reinterpret_cast<const float4*>(&Vb[(size_t)(s0 + r) * DM + c]);
        }
        __syncthreads();
#pragma unroll 8
        for (int s = 0; s < 32; ++s) {
            float4 kv = *reinterpret_cast<const float4*>(&Ks[s][ty * 4]);
            float4 vv = *reinterpret_cast<const float4*>(&Vs[s][tx * 4]);
            float ka[4] = {kv.x, kv.y, kv.z, kv.w};
            float va[4] = {vv.x, vv.y, vv.z, vv.w};
#pragma unroll
            for (int i = 0; i < 4; ++i)
#pragma unroll
                for (int j = 0; j < 4; ++j)
                    acc[i][j] = fmaf(ka[i], va[j], acc[i][j]);
        }
        __syncthreads();
    }

    float* Pp = g_Mpart[bh][chunk];
#pragma unroll
    for (int i = 0; i < 4; ++i)
#pragma unroll
        for (int j = 0; j < 4; ++j)
            Pp[(ty * 4 + i) * DK + tx * 4 + j] = acc[i][j];
}

// deterministic reduce: M = 0.125 * sum_chunks P
__global__ __launch_bounds__(256)
void ktv_reduce(float* __restrict__ Mh)
{
    int o = blockIdx.x * 256 + threadIdx.x;
    int bh = o >> 12;
    int i = o & 4095;
    float s = 0.0f;
#pragma unroll
    for (int c = 0; c < KTV_CHUNKS; ++c) s += g_Mpart[bh][c][i];
    Mh[o] = s * 0.125f;
}

// ---------------------------------------------------------------------------
// qm: O[b,s,h*64+d2] = sum_d1 Q[b,s,h*64+d1] * M[bh][d1][d2]
// ---------------------------------------------------------------------------
__global__ __launch_bounds__(256)
void qm_kernel(const float* __restrict__ Q, const float* __restrict__ Mh,
               float* __restrict__ O)
{
    const int bh = blockIdx.y;
    const int b = bh >> 4, h = bh & 15;
    const int s0 = blockIdx.x * 64;

    __shared__ float Ms[DK][DK];
    __shared__ float Qs[64][DK];

    const float* Qb = Q + (size_t)b * S_SZ * DM + h * DK;
    const float* Mp = Mh + (size_t)bh * DK * DK;

    const int tid = threadIdx.x;
#pragma unroll
    for (int i = 0; i < 4; ++i) {
        int idx = tid + i * 256;
        int r = idx >> 4;
        int c = (idx & 15) * 4;
        *reinterpret_cast<float4*>(&Ms[r][c]) =
            *reinterpret_cast<const float4*>(&Mp[r * DK + c]);
        *reinterpret_cast<float4*>(&Qs[r][c]) =
            *reinterpret_cast<const float4*>(&Qb[(size_t)(s0 + r) * DM + c]);
    }
    __syncthreads();

    const int tx = tid & 15;
    const int ty = tid >> 4;
    float acc[4][4];
#pragma unroll
    for (int i = 0; i < 4; ++i)
#pragma unroll
        for (int j = 0; j < 4; ++j) acc[i][j] = 0.0f;

#pragma unroll 4
    for (int d = 0; d < DK; d += 4) {
        float4 qv[4], mv[4];
#pragma unroll
        for (int i = 0; i < 4; ++i)
            qv[i] = *reinterpret_cast<const float4*>(&Qs[ty * 4 + i][d]);
#pragma unroll
        for (int e = 0; e < 4; ++e)
            mv[e] = *reinterpret_cast<const float4*>(&Ms[d + e][tx * 4]);
#pragma unroll
        for (int i = 0; i < 4; ++i) {
            float qa[4] = {qv[i].x, qv[i].y, qv[i].z, qv[i].w};
#pragma unroll
            for (int e = 0; e < 4; ++e) {
                acc[i][0] = fmaf(qa[e], mv[e].x, acc[i][0]);
                acc[i][1] = fmaf(qa[e], mv[e].y, acc[i][1]);
                acc[i][2] = fmaf(qa[e], mv[e].z, acc[i][2]);
                acc[i][3] = fmaf(qa[e], mv[e].w, acc[i][3]);
            }
        }
    }

    float* Op = O + (size_t)b * S_SZ * DM + (size_t)s0 * DM + h * DK;
#pragma unroll
    for (int i = 0; i < 4; ++i) {
        float4 v = {acc[i][0], acc[i][1], acc[i][2], acc[i][3]};
        *reinterpret_cast<float4*>(&Op[(size_t)(ty * 4 + i) * DM + tx * 4]) = v;
    }
}

// ---------------------------------------------------------------------------
// Launch
// ---------------------------------------------------------------------------
extern "C" void kernel_launch(void* const* d_in, const int* in_sizes, int n_in,
                              void* d_out, int out_size)
{
    const float* query = (const float*)d_in[0];
    const float* key   = (const float*)d_in[1];
    const float* value = (const float*)d_in[2];
    // d_in[3] = mask (unused by reference)
    const float* Wq = (const float*)d_in[4];
    const float* Wk = (const float*)d_in[5];
    const float* Wv = (const float*)d_in[6];
    const float* Wo = (const float*)d_in[7];
    float* out = (float*)d_out;

    float *pQ, *pK, *pV, *pO, *pM;
    cudaGetSymbolAddress((void**)&pQ, g_Q);
    cudaGetSymbolAddress((void**)&pK, g_K);
    cudaGetSymbolAddress((void**)&pV, g_V);
    cudaGetSymbolAddress((void**)&pO, g_O);
    cudaGetSymbolAddress((void**)&pM, g_M);

    cudaFuncSetAttribute(qkv_gemm, cudaFuncAttributeMaxDynamicSharedMemorySize, SM_DYN);
    cudaFuncSetAttribute(out_gemm, cudaFuncAttributeMaxDynamicSharedMemorySize, SM_DYN);

    dim3 blk(256);

    // Q/K/V projections, merged launch
    dim3 gridQKV(DM / TBN, BS / TBM, 3);   // (4, 32, 3)
    qkv_gemm<<<gridQKV, blk, SM_DYN>>>(query, key, value, Wq, Wk, Wv);

    // M = (K^T V)/8 per (b,h)
    dim3 gridKTV(KTV_CHUNKS, B_SZ * NH);
    ktv_partial<<<gridKTV, blk>>>(pK, pV);
    ktv_reduce<<<(B_SZ * NH * DK * DK) / 256, blk>>>(pM);

    // O = Q M per (b,h)
    dim3 gridQM(S_SZ / 64, B_SZ * NH);
    qm_kernel<<<gridQM, blk>>>(pQ, pM, pO);

    // final = O Wo^T
    dim3 gridO(DM / TBN, BS / TBM, 1);
    out_gemm<<<gridO, blk, SM_DYN>>>(Wo, out);
}

// round 16
// speedup vs baseline: 1.4931x; 1.4931x over previous
#include <cuda_runtime.h>
#include <cuda_bf16.h>
#include <cstdint>

// Problem constants
#define B_SZ   2
#define S_SZ   2048
#define DM     1024
#define NH     16
#define DK     64
#define BS     (B_SZ * S_SZ)          // 4096 rows

#define KTV_CHUNKS 32

// Scratch (no cudaMalloc allowed -> device globals)
__device__ float g_Q[BS * DM];
__device__ float g_K[BS * DM];
__device__ float g_V[BS * DM];
__device__ float g_O[BS * DM];
__device__ float g_M[B_SZ * NH * DK * DK];
__device__ float g_Mpart[B_SZ * NH][KTV_CHUNKS][DK * DK];

// ---------------------------------------------------------------------------
// tf32 mma.sync GEMM: C[M,N] = A[M,K] * W[N,K]^T  (row-major, K contiguous)
// CTA tile 128x256, k-tile 32, 8 warps (2m x 4n), warp tile 64x64.
// cp.async double-buffered smem holding RAW fp32; cvt.rna.tf32 applied at
// fragment-load time (no global staging registers -> no spills).
// ---------------------------------------------------------------------------
#define TBM 128
#define TBN 256
#define TBK 32
#define NKT (DM / TBK)       // 32
#define SPAD 36              // row stride 144B (16B aligned, conflict-free LDS)
#define SM_DYN (2 * (TBM + TBN) * SPAD * 4)   // 110592 bytes

__device__ __forceinline__ uint32_t f2tf32(float f) {
    uint32_t r;
    asm("cvt.rna.tf32.f32 %0, %1;" : "=r"(r) : "f"(f));
    return r;
}

__device__ __forceinline__ uint32_t smem_u32(const void* p) {
    uint32_t a;
    asm("{ .reg .u64 t; cvta.to.shared.u64 t, %1; cvt.u32.u64 %0, t; }" : "=r"(a) : "l"(p));
    return a;
}

__device__ __forceinline__ void cp_async16(uint32_t dst, const void* src) {
    asm volatile("cp.async.cg.shared.global [%0], [%1], 16;\n" :: "r"(dst), "l"(src));
}

__device__ __forceinline__ void mma_tf32(float* c, const uint32_t* a, const uint32_t* b) {
    asm volatile(
        "mma.sync.aligned.m16n8k8.row.col.f32.tf32.tf32.f32 "
        "{%0,%1,%2,%3}, {%4,%5,%6,%7}, {%8,%9}, {%0,%1,%2,%3};\n"
        : "+f"(c[0]), "+f"(c[1]), "+f"(c[2]), "+f"(c[3])
        : "r"(a[0]), "r"(a[1]), "r"(a[2]), "r"(a[3]), "r"(b[0]), "r"(b[1]));
}

__device__ __forceinline__
void gemm_body(const float* __restrict__ A, const float* __restrict__ W,
               float* __restrict__ C, int bm, int bn)
{
    extern __shared__ float sm[];
    float* As = sm;                        // [2][128][SPAD]
    float* Ws = sm + 2 * TBM * SPAD;       // [2][256][SPAD]

    const uint32_t as_base = smem_u32(As);
    const uint32_t ws_base = smem_u32(Ws);

    const int tid  = threadIdx.x;
    const int lane = tid & 31;
    const int wid  = tid >> 5;
    const int g    = lane >> 2;       // 0..7
    const int t    = lane & 3;        // 0..3
    const int wm   = wid >> 2;        // 0..1  (64-row m-tile)
    const int wn   = wid & 3;         // 0..3  (64-col n-tile)

    // per-thread copy slots: A 4 float4s, B 8 float4s
    const int cr = tid >> 3;          // 0..31 row base (A rows r = cr + 32i? no: see below)
    const int cc = (tid & 7) * 4;     // 0..28 col (words)
    (void)cr;

    float acc[4][8][4];
#pragma unroll
    for (int mi = 0; mi < 4; ++mi)
#pragma unroll
        for (int ni = 0; ni < 8; ++ni)
#pragma unroll
            for (int e = 0; e < 4; ++e) acc[mi][ni][e] = 0.0f;

    // issue cp.async for tile kt into buffer buf
    auto issue_tile = [&](int kt, int buf) {
        const int k0 = kt * TBK;
        const uint32_t ab = as_base + (uint32_t)buf * TBM * SPAD * 4;
        const uint32_t wb = ws_base + (uint32_t)buf * TBN * SPAD * 4;
#pragma unroll
        for (int i = 0; i < 4; ++i) {                   // A: 1024 float4
            int idx = tid + i * 256;
            int r = idx >> 3, c = (idx & 7) * 4;
            cp_async16(ab + (uint32_t)(r * SPAD + c) * 4,
                       &A[(size_t)(bm + r) * DM + k0 + c]);
        }
#pragma unroll
        for (int i = 0; i < 8; ++i) {                   // B: 2048 float4
            int idx = tid + i * 256;
            int r = idx >> 3, c = (idx & 7) * 4;
            cp_async16(wb + (uint32_t)(r * SPAD + c) * 4,
                       &W[(size_t)(bn + r) * DM + k0 + c]);
        }
        asm volatile("cp.async.commit_group;\n" ::: "memory");
    };

    // prologue: fill both buffers
    issue_tile(0, 0);
    issue_tile(1, 1);

    for (int kt = 0; kt < NKT; ++kt) {
        if (kt + 1 < NKT) {
            asm volatile("cp.async.wait_group 1;\n" ::: "memory");
        } else {
            asm volatile("cp.async.wait_group 0;\n" ::: "memory");
        }
        __syncthreads();

        const float* Ab = As + (kt & 1) * TBM * SPAD;
        const float* Wb = Ws + (kt & 1) * TBN * SPAD;

        // ---- compute: 4 k-steps of 8 ----
#pragma unroll
        for (int ks = 0; ks < 4; ++ks) {
            const int kk = ks * 8;
            uint32_t af[4][4];
#pragma unroll
            for (int mi = 0; mi < 4; ++mi) {
                int m = wm * 64 + mi * 16 + g;
                af[mi][0] = f2tf32(Ab[m * SPAD + kk + t]);
                af[mi][1] = f2tf32(Ab[(m + 8) * SPAD + kk + t]);
                af[mi][2] = f2tf32(Ab[m * SPAD + kk + t + 4]);
                af[mi][3] = f2tf32(Ab[(m + 8) * SPAD + kk + t + 4]);
            }
            uint32_t bf[8][2];
#pragma unroll
            for (int ni = 0; ni < 8; ++ni) {
                int n = wn * 64 + ni * 8 + g;
                bf[ni][0] = f2tf32(Wb[n * SPAD + kk + t]);
                bf[ni][1] = f2tf32(Wb[n * SPAD + kk + t + 4]);
            }
#pragma unroll
            for (int mi = 0; mi < 4; ++mi)
#pragma unroll
                for (int ni = 0; ni < 8; ++ni)
                    mma_tf32(acc[mi][ni], af[mi], bf[ni]);
        }
        __syncthreads();

        if (kt + 2 < NKT) issue_tile(kt + 2, kt & 1);
    }

    // ---- epilogue ----
#pragma unroll
    for (int mi = 0; mi < 4; ++mi) {
#pragma unroll
        for (int ni = 0; ni < 8; ++ni) {
            int row = bm + wm * 64 + mi * 16 + g;
            int col = bn + wn * 64 + ni * 8 + 2 * t;
            *reinterpret_cast<float2*>(&C[(size_t)row * DM + col]) =
                make_float2(acc[mi][ni][0], acc[mi][ni][1]);
            *reinterpret_cast<float2*>(&C[(size_t)(row + 8) * DM + col]) =
                make_float2(acc[mi][ni][2], acc[mi][ni][3]);
        }
    }
}

// Merged Q/K/V projection: blockIdx.z selects which projection
__global__ __launch_bounds__(256, 1)
void qkv_gemm(const float* __restrict__ q, const float* __restrict__ k,
              const float* __restrict__ v,
              const float* __restrict__ Wq, const float* __restrict__ Wk,
              const float* __restrict__ Wv)
{
    const float* A;
    const float* W;
    float* C;
    if (blockIdx.z == 0)      { A = q; W = Wq; C = g_Q; }
    else if (blockIdx.z == 1) { A = k; W = Wk; C = g_K; }
    else                      { A = v; W = Wv; C = g_V; }
    gemm_body(A, W, C, blockIdx.y * TBM, blockIdx.x * TBN);
}

__global__ __launch_bounds__(256, 1)
void out_gemm(const float* __restrict__ Wo, float* __restrict__ out)
{
    gemm_body(g_O, Wo, out, blockIdx.y * TBM, blockIdx.x * TBN);
}

// ---------------------------------------------------------------------------
// ktv partial: P[bh][chunk][d1][d2] = sum_{s in chunk} K[b,s,h,d1]*V[b,s,h,d2]
// ---------------------------------------------------------------------------
__global__ __launch_bounds__(256)
void ktv_partial(const float* __restrict__ Km, const float* __restrict__ Vm)
{
    const int chunk = blockIdx.x;
    const int bh = blockIdx.y;
    const int b = bh >> 4, h = bh & 15;
    const int sbase = chunk * (S_SZ / KTV_CHUNKS);
    const float* Kb = Km + (size_t)b * S_SZ * DM + h * DK;
    const float* Vb = Vm + (size_t)b * S_SZ * DM + h * DK;

    __shared__ float Ks[32][DK];
    __shared__ float Vs[32][DK];

    const int tid = threadIdx.x;
    const int tx = tid & 15;
    const int ty = tid >> 4;

    float acc[4][4];
#pragma unroll
    for (int i = 0; i < 4; ++i)
#pragma unroll
        for (int j = 0; j < 4; ++j) acc[i][j] = 0.0f;

    for (int s0 = sbase; s0 < sbase + S_SZ / KTV_CHUNKS; s0 += 32) {
#pragma unroll
        for (int i = 0; i < 2; ++i) {
            int idx = tid + i * 256;
            int r = idx >> 4;
            int c = (idx & 15) * 4;
            *reinterpret_cast<float4*>(&Ks[r][c]) =
                *reinterpret_cast<const float4*>(&Kb[(size_t)(s0 + r) * DM + c]);
            *reinterpret_cast<float4*>(&Vs[r][c]) =
                *reinterpret_cast<const float4*>(&Vb[(size_t)(s0 + r) * DM + c]);
        }
        __syncthreads();
#pragma unroll 8
        for (int s = 0; s < 32; ++s) {
            float4 kv = *reinterpret_cast<const float4*>(&Ks[s][ty * 4]);
            float4 vv = *reinterpret_cast<const float4*>(&Vs[s][tx * 4]);
            float ka[4] = {kv.x, kv.y, kv.z, kv.w};
            float va[4] = {vv.x, vv.y, vv.z, vv.w};
#pragma unroll
            for (int i = 0; i < 4; ++i)
#pragma unroll
                for (int j = 0; j < 4; ++j)
                    acc[i][j] = fmaf(ka[i], va[j], acc[i][j]);
        }
        __syncthreads();
    }

    float* Pp = g_Mpart[bh][chunk];
#pragma unroll
    for (int i = 0; i < 4; ++i)
#pragma unroll
        for (int j = 0; j < 4; ++j)
            Pp[(ty * 4 + i) * DK + tx * 4 + j] = acc[i][j];
}

// deterministic reduce: M = 0.125 * sum_chunks P
__global__ __launch_bounds__(256)
void ktv_reduce(float* __restrict__ Mh)
{
    int o = blockIdx.x * 256 + threadIdx.x;
    int bh = o >> 12;
    int i = o & 4095;
    float s = 0.0f;
#pragma unroll
    for (int c = 0; c < KTV_CHUNKS; ++c) s += g_Mpart[bh][c][i];
    Mh[o] = s * 0.125f;
}

// ---------------------------------------------------------------------------
// qm: O[b,s,h*64+d2] = sum_d1 Q[b,s,h*64+d1] * M[bh][d1][d2]
// ---------------------------------------------------------------------------
__global__ __launch_bounds__(256)
void qm_kernel(const float* __restrict__ Q, const float* __restrict__ Mh,
               float* __restrict__ O)
{
    const int bh = blockIdx.y;
    const int b = bh >> 4, h = bh & 15;
    const int s0 = blockIdx.x * 64;

    __shared__ float Ms[DK][DK];
    __shared__ float Qs[64][DK];

    const float* Qb = Q + (size_t)b * S_SZ * DM + h * DK;
    const float* Mp = Mh + (size_t)bh * DK * DK;

    const int tid = threadIdx.x;
#pragma unroll
    for (int i = 0; i < 4; ++i) {
        int idx = tid + i * 256;
        int r = idx >> 4;
        int c = (idx & 15) * 4;
        *reinterpret_cast<float4*>(&Ms[r][c]) =
            *reinterpret_cast<const float4*>(&Mp[r * DK + c]);
        *reinterpret_cast<float4*>(&Qs[r][c]) =
            *reinterpret_cast<const float4*>(&Qb[(size_t)(s0 + r) * DM + c]);
    }
    __syncthreads();

    const int tx = tid & 15;
    const int ty = tid >> 4;
    float acc[4][4];
#pragma unroll
    for (int i = 0; i < 4; ++i)
#pragma unroll
        for (int j = 0; j < 4; ++j) acc[i][j] = 0.0f;

#pragma unroll 4
    for (int d = 0; d < DK; d += 4) {
        float4 qv[4], mv[4];
#pragma unroll
        for (int i = 0; i < 4; ++i)
            qv[i] = *reinterpret_cast<const float4*>(&Qs[ty * 4 + i][d]);
#pragma unroll
        for (int e = 0; e < 4; ++e)
            mv[e] = *reinterpret_cast<const float4*>(&Ms[d + e][tx * 4]);
#pragma unroll
        for (int i = 0; i < 4; ++i) {
            float qa[4] = {qv[i].x, qv[i].y, qv[i].z, qv[i].w};
#pragma unroll
            for (int e = 0; e < 4; ++e) {
                acc[i][0] = fmaf(qa[e], mv[e].x, acc[i][0]);
                acc[i][1] = fmaf(qa[e], mv[e].y, acc[i][1]);
                acc[i][2] = fmaf(qa[e], mv[e].z, acc[i][2]);
                acc[i][3] = fmaf(qa[e], mv[e].w, acc[i][3]);
            }
        }
    }

    float* Op = O + (size_t)b * S_SZ * DM + (size_t)s0 * DM + h * DK;
#pragma unroll
    for (int i = 0; i < 4; ++i) {
        float4 v = {acc[i][0], acc[i][1], acc[i][2], acc[i][3]};
        *reinterpret_cast<float4*>(&Op[(size_t)(ty * 4 + i) * DM + tx * 4]) = v;
    }
}

// ---------------------------------------------------------------------------
// Launch
// ---------------------------------------------------------------------------
extern "C" void kernel_launch(void* const* d_in, const int* in_sizes, int n_in,
                              void* d_out, int out_size)
{
    const float* query = (const float*)d_in[0];
    const float* key   = (const float*)d_in[1];
    const float* value = (const float*)d_in[2];
    // d_in[3] = mask (unused by reference)
    const float* Wq = (const float*)d_in[4];
    const float* Wk = (const float*)d_in[5];
    const float* Wv = (const float*)d_in[6];
    const float* Wo = (const float*)d_in[7];
    float* out = (float*)d_out;

    float *pQ, *pK, *pV, *pO, *pM;
    cudaGetSymbolAddress((void**)&pQ, g_Q);
    cudaGetSymbolAddress((void**)&pK, g_K);
    cudaGetSymbolAddress((void**)&pV, g_V);
    cudaGetSymbolAddress((void**)&pO, g_O);
    cudaGetSymbolAddress((void**)&pM, g_M);

    cudaFuncSetAttribute(qkv_gemm, cudaFuncAttributeMaxDynamicSharedMemorySize, SM_DYN);
    cudaFuncSetAttribute(out_gemm, cudaFuncAttributeMaxDynamicSharedMemorySize, SM_DYN);

    dim3 blk(256);

    // Q/K/V projections, merged launch
    dim3 gridQKV(DM / TBN, BS / TBM, 3);   // (4, 32, 3)
    qkv_gemm<<<gridQKV, blk, SM_DYN>>>(query, key, value, Wq, Wk, Wv);

    // M = (K^T V)/8 per (b,h)
    dim3 gridKTV(KTV_CHUNKS, B_SZ * NH);
    ktv_partial<<<gridKTV, blk>>>(pK, pV);
    ktv_reduce<<<(B_SZ * NH * DK * DK) / 256, blk>>>(pM);

    // O = Q M per (b,h)
    dim3 gridQM(S_SZ / 64, B_SZ * NH);
    qm_kernel<<<gridQM, blk>>>(pQ, pM, pO);

    // final = O Wo^T
    dim3 gridO(DM / TBN, BS / TBM, 1);
    out_gemm<<<gridO, blk, SM_DYN>>>(Wo, out);
}